// round 15
// baseline (speedup 1.0000x reference)
#include <cuda_runtime.h>

#define BT     4096      // B*T
#define KCAND  64
#define DK     128
#define DCTX   256
#define DV     128
#define GAMMA  1.0f
#define ETA    1.0f

#define CHUNK   8        // candidates per pipeline stage
#define NCHUNK  8        // KCAND / CHUNK
// stage floats: K 1024 | ctx 2048 | rel 1024 | ent 1024  = 5120 (V separate)
#define STAGE_F 5120
#define NBLK    592      // 4 blocks/SM x 148 SMs, single wave
#define NRMAX   7        // max rows per block (4096/592 -> 6 or 7)

// smem: 2 stages + 2 V buffers + 2 sS + 2 id/tau buffers + Q tile
#define SMEM_FLOATS (2*STAGE_F + 2*1024 + 2*64 + 512 + NRMAX*DK)
#define SMEM_BYTES  (SMEM_FLOATS * 4)    // 55296 B -> 4 blocks/SM

// 4 MB scratch for Qw rows; each block writes only the rows it later reads
// (same-CTA produce/consume; __syncthreads orders global accesses cta-wide).
__device__ float g_qw[BT * DCTX];

#define CP_ASYNC_CG16(dst, src) \
    asm volatile("cp.async.cg.shared.global [%0], [%1], 16;\n" :: "r"(dst), "l"(src))
#define CP_ASYNC_COMMIT() asm volatile("cp.async.commit_group;\n" ::)
#define CP_ASYNC_WAIT(N)  asm volatile("cp.async.wait_group %0;\n" :: "n"(N))

__device__ __forceinline__ unsigned smem_u32(const void* p) {
    return (unsigned)__cvta_generic_to_shared(p);
}

// ---------------------------------------------------------------------------
// Single fused persistent kernel, software-pipelined softmax/V:
// phase t = [barrier] -> scores(chunk t) + V-accumulate(chunk t-1) ->
//           [barrier] -> issue stage(t+2) + V(t+1) in one commit group.
// V copies run one chunk behind stage copies so V data survives the extra
// phase it is needed. esum accumulates in registers during the V phase, so
// the row epilogue (folded into the next row's first phase) is just a
// normalize + store.
// ---------------------------------------------------------------------------
__global__ __launch_bounds__(256, 4) void kb_fused_kernel(
    const float* __restrict__ Q,
    const float* __restrict__ K_kb,
    const float* __restrict__ V_kb,
    const float* __restrict__ ctx,
    const float* __restrict__ W_ctx,
    const float* __restrict__ b_ctx,
    const float* __restrict__ rel_emb,
    const float* __restrict__ ent_emb,
    const float* __restrict__ q_min,
    const float* __restrict__ q_max,
    const float* __restrict__ tau_min,
    const float* __restrict__ tau_max,
    const int*   __restrict__ rel_id,
    const int*   __restrict__ ent_id,
    float* __restrict__ out_alpha,
    float* __restrict__ out_v)
{
    extern __shared__ float smem[];
    float* sA   = smem;                       // [2][STAGE_F]
    float* sV   = smem + 2 * STAGE_F;         // [2][1024]
    float* sS   = sV + 2048;                  // [2][64] e-values per row
    int*   sIds = (int*)(sS + 128);           // [2][256]: rid|eid|tmin|tmax
    float* sQt  = (float*)(sIds + 512);       // [NRMAX][DK]

    const int tid  = threadIdx.x;
    const int warp = tid >> 5;
    const int lane = tid & 31;

    const int b  = blockIdx.x;
    const int r0 = (b * BT) / NBLK;
    const int r1 = ((b + 1) * BT) / NBLK;
    const int nr = r1 - r0;
    const int T  = nr * NCHUNK - 1;           // last relative chunk index

    auto load_small = [&](int row, int bufsel) {
        int* B = sIds + bufsel * 256;
        if (tid < 64)        B[tid]            = rel_id[row * KCAND + tid];
        else if (tid < 128)  B[tid]            = ent_id[row * KCAND + tid - 64];
        else if (tid < 192)  ((float*)B)[tid]  = tau_min[row * KCAND + tid - 128];
        else                 ((float*)B)[tid]  = tau_max[row * KCAND + tid - 192];
    };

    // stage f4 map: K [0,256) | ctx [256,768) | rel [768,1024) | ent [1024,1280)
    auto issue_stage = [&](int t2) {
        const int ri2 = t2 >> 3;
        const int c2  = t2 & 7;
        const int row = r0 + ri2;
        const int kc  = c2 * CHUNK;
        const long bk = (long)row * KCAND * DK;
        const long bc = (long)row * KCAND * DCTX;
        const unsigned dst = smem_u32(sA + (t2 & 1) * STAGE_F);
        const int* Rid = sIds + (ri2 & 1) * 256;
        const int* Eid = Rid + 64;
        { const int cand = tid >> 5, off = tid & 31;                      // K
          CP_ASYNC_CG16(dst + tid * 16,
                        K_kb + bk + (long)(kc + cand) * DK + off * 4); }
        { const int cand = tid >> 6, off = tid & 63;                      // ctx lo
          CP_ASYNC_CG16(dst + (256 + tid) * 16,
                        ctx + bc + (long)(kc + cand) * DCTX + off * 4); }
        { const int tt = tid + 256; const int cand = tt >> 6, off = tt & 63;
          CP_ASYNC_CG16(dst + (256 + tt) * 16,                            // ctx hi
                        ctx + bc + (long)(kc + cand) * DCTX + off * 4); }
        { const int cand = tid >> 5, off = tid & 31;                      // rel
          CP_ASYNC_CG16(dst + (768 + tid) * 16,
                        rel_emb + (long)Rid[kc + cand] * DK + off * 4); }
        { const int cand = tid >> 5, off = tid & 31;                      // ent
          CP_ASYNC_CG16(dst + (1024 + tid) * 16,
                        ent_emb + (long)Eid[kc + cand] * DK + off * 4); }
    };
    auto issue_V = [&](int t1) {
        const int ri1 = t1 >> 3;
        const int c1  = t1 & 7;
        const int row = r0 + ri1;
        const long bk = (long)row * KCAND * DK;
        const int  kc = c1 * CHUNK;
        const unsigned dst = smem_u32(sV + (t1 & 1) * 1024);
        const int cand = tid >> 5, off = tid & 31;
        CP_ASYNC_CG16(dst + tid * 16,
                      V_kb + bk + (long)(kc + cand) * DV + off * 4);
    };

    // ---- prologue: row0 small data + Q tile, then start streaming ----
    load_small(r0, 0);
    for (int i = tid; i < nr * DK; i += 256)
        sQt[i] = Q[(long)(r0 + (i >> 7)) * DK + (i & 127)];
    __syncthreads();

    issue_stage(0);             CP_ASYNC_COMMIT();   // group: stage0
    issue_stage(1); issue_V(0); CP_ASYNC_COMMIT();   // group: stage1 + V0

    // ---- Qw for this block's rows (W read ONCE per block), overlapped with
    // the in-flight copies. thread = 4 cols x rows {rs, rs+4}.
    {
        const int rs = tid >> 6;          // 0..3
        const int cg = tid & 63;          // float4 col group
        const bool h0 = rs < nr, h1 = (rs + 4) < nr;
        const float4* W4 = (const float4*)W_ctx;
        float4 a0 = make_float4(0.f, 0.f, 0.f, 0.f), a1 = a0;
#pragma unroll 4
        for (int d = 0; d < DK; ++d) {
            const float4 wv = W4[d * 64 + cg];              // coalesced, L2
            const float q0 = h0 ? sQt[rs * DK + d] : 0.f;
            const float q1 = h1 ? sQt[(rs + 4) * DK + d] : 0.f;
            a0.x = fmaf(q0, wv.x, a0.x); a0.y = fmaf(q0, wv.y, a0.y);
            a0.z = fmaf(q0, wv.z, a0.z); a0.w = fmaf(q0, wv.w, a0.w);
            a1.x = fmaf(q1, wv.x, a1.x); a1.y = fmaf(q1, wv.y, a1.y);
            a1.z = fmaf(q1, wv.z, a1.z); a1.w = fmaf(q1, wv.w, a1.w);
        }
        if (h0) ((float4*)(g_qw + (long)(r0 + rs) * DCTX))[cg] = a0;
        if (h1) ((float4*)(g_qw + (long)(r0 + rs + 4) * DCTX))[cg] = a1;
    }
    __syncthreads();   // g_qw writes ordered before same-block reads

    const float inv_sqrt = 0.08838834764831843f;   // 1/sqrt(128)
    const float4 bv = ((const float4*)b_ctx)[lane];

    float accV = 0.f, esum = 0.f;

    // =========================== row loop ===============================
    for (int ri = 0; ri < nr; ++ri) {
        const int row = r0 + ri;

        // per-row query-side registers (direct coalesced LDG, L2-hot)
        const float4 qv  = ((const float4*)(Q    + (long)row * DK))[lane];
        const float4 qwa = ((const float4*)(g_qw + (long)row * DCTX))[lane];
        const float4 qwb = ((const float4*)(g_qw + (long)row * DCTX))[lane + 32];
        float qb = qv.x * bv.x + qv.y * bv.y + qv.z * bv.z + qv.w * bv.w;
#pragma unroll
        for (int off = 16; off; off >>= 1) qb += __shfl_xor_sync(~0u, qb, off);
        const float qmn = q_min[row];
        const float qmx = q_max[row];
        const float* Tmin = (const float*)(sIds + (ri & 1) * 256) + 128;
        const float* Tmax = Tmin + 64;

        for (int c = 0; c < NCHUNK; ++c) {
            const int t = ri * NCHUNK + c;
            CP_ASYNC_WAIT(1);
            __syncthreads();    // chunk t stage + chunk t-1 V + t-1 e's visible

            // ---- scores: 8 warps x 1 candidate of chunk t ----
            {
                const float* S = sA + (t & 1) * STAGE_F;
                const int kc = c * CHUNK;
                const int k  = kc + warp;

                const float4 kv = ((const float4*)S)[warp * 32 + lane];
                const float4 c0 = ((const float4*)(S + 1024))[warp * 64 + lane];
                const float4 c1 = ((const float4*)(S + 1024))[warp * 64 + lane + 32];
                const float4 rv = ((const float4*)(S + 3072))[warp * 32 + lane];
                const float4 ev = ((const float4*)(S + 4096))[warp * 32 + lane];

                float sem = qv.x * kv.x + qv.y * kv.y + qv.z * kv.z + qv.w * kv.w;
                float cx  = qv.x * (rv.x + ev.x) + qv.y * (rv.y + ev.y)
                          + qv.z * (rv.z + ev.z) + qv.w * (rv.w + ev.w);
                cx += qwa.x * c0.x + qwa.y * c0.y + qwa.z * c0.z + qwa.w * c0.w;
                cx += qwb.x * c1.x + qwb.y * c1.y + qwb.z * c1.z + qwb.w * c1.w;

                float tot = sem + GAMMA * cx;
#pragma unroll
                for (int off = 16; off; off >>= 1)
                    tot += __shfl_xor_sync(~0u, tot, off);

                if (lane == 0) {
                    const float tmin = Tmin[k];
                    const float tmax = Tmax[k];
                    const float inter = fmaxf(fminf(qmx, tmax) - fmaxf(qmn, tmin), 0.f);
                    const float uni   = fmaxf(qmx, tmax) - fminf(qmn, tmin);
                    const float s = (tot + GAMMA * qb) * inv_sqrt
                                  + ETA * (inter / (uni + 1e-6f));
                    sS[(ri & 1) * 64 + k] = __expf(s);  // |s| small: safe
                }
            }

            // ---- V accumulate of chunk t-1 (threads 0..127) ----
            if (t > 0 && tid < DV) {
                const int tp  = t - 1;
                const int pri = tp >> 3;
                const int pcc = tp & 7;
                const float* E  = sS + (pri & 1) * 64 + pcc * CHUNK;
                const float* Vs = sV + (tp & 1) * 1024;
                const float e0 = E[0], e1 = E[1], e2 = E[2], e3 = E[3];
                const float e4 = E[4], e5 = E[5], e6 = E[6], e7 = E[7];
                accV = fmaf(e0, Vs[0 * DV + tid], accV);
                accV = fmaf(e1, Vs[1 * DV + tid], accV);
                accV = fmaf(e2, Vs[2 * DV + tid], accV);
                accV = fmaf(e3, Vs[3 * DV + tid], accV);
                accV = fmaf(e4, Vs[4 * DV + tid], accV);
                accV = fmaf(e5, Vs[5 * DV + tid], accV);
                accV = fmaf(e6, Vs[6 * DV + tid], accV);
                accV = fmaf(e7, Vs[7 * DV + tid], accV);
                esum += (e0 + e1 + e2 + e3) + (e4 + e5 + e6 + e7);

                // prev chunk closed row ri-1 -> epilogue (normalize + store)
                if (pcc == 7) {
                    const int prow = row - 1;
                    const float inv = 1.0f / esum;
                    out_v[(long)prow * DV + tid] = accV * inv;
                    if (tid < KCAND)
                        out_alpha[prow * KCAND + tid] =
                            sS[(pri & 1) * 64 + tid] * inv;
                    accV = 0.f; esum = 0.f;
                }
            }
            __syncthreads();    // stage t + V(t-1) consumed before reuse

            // ---- issue: stage t+2 and V t+1 in one commit group ----
            {
                const int t2 = t + 2;
                const bool hs = (t2 <= T);
                const bool hv = (t + 1 <= T);
                if (hs) issue_stage(t2);
                if (hv) issue_V(t + 1);
                if (hs || hv) CP_ASYNC_COMMIT();
            }
            if (c == 4 && ri + 1 < nr) load_small(row + 1, (ri + 1) & 1);
        }
    }

    // ---- tail: final V group, accumulate chunk T, last-row epilogue ----
    CP_ASYNC_WAIT(0);
    __syncthreads();
    if (tid < DV) {
        const int pri = nr - 1;
        const float* E  = sS + (pri & 1) * 64 + 7 * CHUNK;
        const float* Vs = sV + (T & 1) * 1024;
        const float e0 = E[0], e1 = E[1], e2 = E[2], e3 = E[3];
        const float e4 = E[4], e5 = E[5], e6 = E[6], e7 = E[7];
        accV = fmaf(e0, Vs[0 * DV + tid], accV);
        accV = fmaf(e1, Vs[1 * DV + tid], accV);
        accV = fmaf(e2, Vs[2 * DV + tid], accV);
        accV = fmaf(e3, Vs[3 * DV + tid], accV);
        accV = fmaf(e4, Vs[4 * DV + tid], accV);
        accV = fmaf(e5, Vs[5 * DV + tid], accV);
        accV = fmaf(e6, Vs[6 * DV + tid], accV);
        accV = fmaf(e7, Vs[7 * DV + tid], accV);
        esum += (e0 + e1 + e2 + e3) + (e4 + e5 + e6 + e7);

        const int prow = r0 + pri;
        const float inv = 1.0f / esum;
        out_v[(long)prow * DV + tid] = accV * inv;
        if (tid < KCAND)
            out_alpha[prow * KCAND + tid] = sS[(pri & 1) * 64 + tid] * inv;
    }
}

// ---------------------------------------------------------------------------
extern "C" void kernel_launch(void* const* d_in, const int* in_sizes, int n_in,
                              void* d_out, int out_size) {
    const float* Q     = (const float*)d_in[0];
    const float* K_kb  = (const float*)d_in[1];
    const float* V_kb  = (const float*)d_in[2];
    const float* ctx   = (const float*)d_in[3];
    const float* W     = (const float*)d_in[4];
    const float* b_ctx = (const float*)d_in[5];
    const float* rel   = (const float*)d_in[6];
    const float* ent   = (const float*)d_in[7];
    const float* qmin  = (const float*)d_in[8];
    const float* qmax  = (const float*)d_in[9];
    const float* tmin  = (const float*)d_in[10];
    const float* tmax  = (const float*)d_in[11];
    const int*   rid   = (const int*)d_in[12];
    const int*   eid   = (const int*)d_in[13];

    float* out       = (float*)d_out;
    float* out_alpha = out;                    // [BT, 64]
    float* out_v     = out + BT * KCAND;       // [BT, 128]

    cudaFuncSetAttribute(kb_fused_kernel,
                         cudaFuncAttributeMaxDynamicSharedMemorySize,
                         SMEM_BYTES);

    kb_fused_kernel<<<NBLK, 256, SMEM_BYTES>>>(Q, K_kb, V_kb, ctx, W, b_ctx,
                                               rel, ent, qmin, qmax, tmin, tmax,
                                               rid, eid, out_alpha, out_v);
}